// round 6
// baseline (speedup 1.0000x reference)
#include <cuda_runtime.h>

// CostVolume: B=4, C=32, Cr=16, H=64, W=128, D=48
// out[b, ch, d, h, w]:
//   ch in [0,32):   0.25*(left[b,ch,h,w]-right[b,ch,h,w-d])^2   if w>=d else 0
//   ch in [32,48):  reduce_left[b,ch-32,h,w]                     if w>=d else 0
//   ch in [48,64):  reduce_right[b,ch-48,h,w-d]                  if w>=d else 0
//
// 1 row per CTA. Warp-resident rows; ALL window shuffles hoisted up front
// (9 elements cover the warp's 6 d-steps), so the 6 STG.128 issue back-to-back.
// Stores use st.global.cs (evict-first streaming; output is write-once).

#define BB 4
#define CC 32
#define CRR 16
#define HH 64
#define WW 128
#define DD 48
#define CH_TOTAL 64   // C + 2*Cr
#define HW (HH * WW)

__device__ __forceinline__ void store_cs(float* p, float4 v) {
    asm volatile("st.global.cs.v4.f32 [%0], {%1,%2,%3,%4};"
                 :: "l"(p), "f"(v.x), "f"(v.y), "f"(v.z), "f"(v.w) : "memory");
}

// Gather row[4*lane + shift] from warp-resident row (r.x..r.w per lane).
// 'shift' is warp-uniform => sub-select uniform; shfl moves across lanes.
// Negative element indices return garbage, masked out by the w>=d predicate.
__device__ __forceinline__ float warp_gather(const float4 r, int shift, int lane) {
    const int e   = (lane << 2) + shift;
    const int lp  = (e >> 2) & 31;
    const int sub = shift & 3;
    float v;
    if      (sub == 0) v = r.x;
    else if (sub == 1) v = r.y;
    else if (sub == 2) v = r.z;
    else               v = r.w;
    return __shfl_sync(0xffffffffu, v, lp);
}

__global__ __launch_bounds__(256, 8) void cost_volume_kernel(
    const float* __restrict__ left,
    const float* __restrict__ rleft,
    const float* __restrict__ right,
    const float* __restrict__ rright,
    float* __restrict__ out)
{
    const int blk  = blockIdx.x;           // b*CH_TOTAL*H + ch*H + h
    const int h    = blk % HH;
    const int tmp  = blk / HH;
    const int ch   = tmp % CH_TOTAL;
    const int b    = tmp / CH_TOTAL;
    const int lane = threadIdx.x & 31;
    const int warp = threadIdx.x >> 5;
    const int w0   = lane << 2;
    const int d0   = warp * 6;             // this warp covers d in [d0, d0+6)

    float* op = out + ((size_t)(b * CH_TOTAL + ch) * DD + d0) * HW + (size_t)h * WW + w0;

    if (ch < CC) {
        const float4 A = *(const float4*)(left  + ((b * CC + ch) * HH + h) * WW + w0);
        const float4 R = *(const float4*)(right + ((b * CC + ch) * HH + h) * WW + w0);

        // g[i] = right[w0 + 3 - d0 - i], i = 0..8. Element j at step s uses g[s+3-j].
        float g[9];
        #pragma unroll
        for (int i = 0; i < 9; i++)
            g[i] = warp_gather(R, 3 - d0 - i, lane);

        #pragma unroll
        for (int s = 0; s < 6; s++) {
            const int d = d0 + s;
            float4 v; float t;
            t = A.x - g[s + 3]; v.x = (w0     >= d) ? 0.25f * t * t : 0.0f;
            t = A.y - g[s + 2]; v.y = (w0 + 1 >= d) ? 0.25f * t * t : 0.0f;
            t = A.z - g[s + 1]; v.z = (w0 + 2 >= d) ? 0.25f * t * t : 0.0f;
            t = A.w - g[s    ]; v.w = (w0 + 3 >= d) ? 0.25f * t * t : 0.0f;
            store_cs(op, v);
            op += HW;
        }
    } else if (ch < CC + CRR) {
        const float4 A = *(const float4*)(rleft + ((b * CRR + (ch - CC)) * HH + h) * WW + w0);
        #pragma unroll
        for (int s = 0; s < 6; s++) {
            const int d = d0 + s;
            float4 v;
            v.x = (w0     >= d) ? A.x : 0.0f;
            v.y = (w0 + 1 >= d) ? A.y : 0.0f;
            v.z = (w0 + 2 >= d) ? A.z : 0.0f;
            v.w = (w0 + 3 >= d) ? A.w : 0.0f;
            store_cs(op, v);
            op += HW;
        }
    } else {
        const float4 R = *(const float4*)(rright + ((b * CRR + (ch - CC - CRR)) * HH + h) * WW + w0);

        float g[9];
        #pragma unroll
        for (int i = 0; i < 9; i++)
            g[i] = warp_gather(R, 3 - d0 - i, lane);

        #pragma unroll
        for (int s = 0; s < 6; s++) {
            const int d = d0 + s;
            float4 v;
            v.x = (w0     >= d) ? g[s + 3] : 0.0f;
            v.y = (w0 + 1 >= d) ? g[s + 2] : 0.0f;
            v.z = (w0 + 2 >= d) ? g[s + 1] : 0.0f;
            v.w = (w0 + 3 >= d) ? g[s    ] : 0.0f;
            store_cs(op, v);
            op += HW;
        }
    }
}

extern "C" void kernel_launch(void* const* d_in, const int* in_sizes, int n_in,
                              void* d_out, int out_size) {
    const float* left   = (const float*)d_in[0];
    const float* rleft  = (const float*)d_in[1];
    const float* right  = (const float*)d_in[2];
    const float* rright = (const float*)d_in[3];
    // d_in[4] = max_disp (int scalar) == 48, baked in as DD.

    const int grid = BB * CH_TOTAL * HH;   // 16384 CTAs
    cost_volume_kernel<<<grid, 256>>>(left, rleft, right, rright, (float*)d_out);
}

// round 7
// speedup vs baseline: 1.4294x; 1.4294x over previous
#include <cuda_runtime.h>

// CostVolume: B=4, C=32, Cr=16, H=64, W=128, D=48
// out[b, ch, d, h, w]:
//   ch in [0,32):   0.25*(left[b,ch,h,w]-right[b,ch,h,w-d])^2   if w>=d else 0
//   ch in [32,48):  reduce_left[b,ch-32,h,w]                     if w>=d else 0
//   ch in [48,64):  reduce_right[b,ch-48,h,w-d]                  if w>=d else 0
//
// Register-resident rows + shuffle sliding window over d (interleaved with
// stores — the shuffles space out STG.128 issue and keep the L1tex write
// queue from saturating; hoisting them regressed 43%, round 6).
// Stores use st.global.cs (evict-first streaming; output is write-once).
// This config measured 57.9us = ~6.96 TB/s stores = LTS/HBM write ceiling.

#define BB 4
#define CC 32
#define CRR 16
#define HH 64
#define WW 128
#define DD 48
#define CH_TOTAL 64   // C + 2*Cr
#define HW (HH * WW)

__device__ __forceinline__ void store_cs(float* p, float4 v) {
    asm volatile("st.global.cs.v4.f32 [%0], {%1,%2,%3,%4};"
                 :: "l"(p), "f"(v.x), "f"(v.y), "f"(v.z), "f"(v.w) : "memory");
}

// Gather row[4*lane + shift] from warp-resident row (r0..r3 per lane).
// 'shift' is warp-uniform => sub-select is uniform; shfl does lane move.
// Negative element indices return garbage, masked by the w>=d predicate.
__device__ __forceinline__ float warp_gather(const float r0, const float r1,
                                             const float r2, const float r3,
                                             int shift, int lane) {
    const int e   = (lane << 2) + shift;
    const int lp  = (e >> 2) & 31;
    const int sub = shift & 3;
    float v;
    if      (sub == 0) v = r0;
    else if (sub == 1) v = r1;
    else if (sub == 2) v = r2;
    else               v = r3;
    return __shfl_sync(0xffffffffu, v, lp);
}

__global__ __launch_bounds__(256, 8) void cost_volume_kernel(
    const float* __restrict__ left,
    const float* __restrict__ rleft,
    const float* __restrict__ right,
    const float* __restrict__ rright,
    float* __restrict__ out)
{
    const int blk  = blockIdx.x;           // b*CH_TOTAL*H + ch*H + h
    const int h    = blk % HH;
    const int tmp  = blk / HH;
    const int ch   = tmp % CH_TOTAL;
    const int b    = tmp / CH_TOTAL;
    const int lane = threadIdx.x & 31;
    const int warp = threadIdx.x >> 5;
    const int w0   = lane << 2;
    const int d0   = warp * 6;             // this warp covers d in [d0, d0+6)

    float* op = out + ((size_t)(b * CH_TOTAL + ch) * DD + d0) * HW + (size_t)h * WW + w0;

    if (ch < CC) {
        const float4 A = *(const float4*)(left  + ((b * CC + ch) * HH + h) * WW + w0);
        const float4 R = *(const float4*)(right + ((b * CC + ch) * HH + h) * WW + w0);

        float Wn0 = warp_gather(R.x, R.y, R.z, R.w,  0 - d0, lane);
        float Wn1 = warp_gather(R.x, R.y, R.z, R.w,  1 - d0, lane);
        float Wn2 = warp_gather(R.x, R.y, R.z, R.w,  2 - d0, lane);
        float Wn3 = warp_gather(R.x, R.y, R.z, R.w,  3 - d0, lane);

        #pragma unroll
        for (int s = 0; s < 6; s++) {
            const int d = d0 + s;
            float4 v; float t;
            t = A.x - Wn0; v.x = (w0     >= d) ? 0.25f * t * t : 0.0f;
            t = A.y - Wn1; v.y = (w0 + 1 >= d) ? 0.25f * t * t : 0.0f;
            t = A.z - Wn2; v.z = (w0 + 2 >= d) ? 0.25f * t * t : 0.0f;
            t = A.w - Wn3; v.w = (w0 + 3 >= d) ? 0.25f * t * t : 0.0f;
            store_cs(op, v);
            op += HW;

            // slide window to d+1: new element right[w0 - (d+1)]
            const float nw = warp_gather(R.x, R.y, R.z, R.w, -(d + 1), lane);
            Wn3 = Wn2; Wn2 = Wn1; Wn1 = Wn0; Wn0 = nw;
        }
    } else if (ch < CC + CRR) {
        const float4 A = *(const float4*)(rleft + ((b * CRR + (ch - CC)) * HH + h) * WW + w0);
        #pragma unroll
        for (int s = 0; s < 6; s++) {
            const int d = d0 + s;
            float4 v;
            v.x = (w0     >= d) ? A.x : 0.0f;
            v.y = (w0 + 1 >= d) ? A.y : 0.0f;
            v.z = (w0 + 2 >= d) ? A.z : 0.0f;
            v.w = (w0 + 3 >= d) ? A.w : 0.0f;
            store_cs(op, v);
            op += HW;
        }
    } else {
        const float4 R = *(const float4*)(rright + ((b * CRR + (ch - CC - CRR)) * HH + h) * WW + w0);

        float Wn0 = warp_gather(R.x, R.y, R.z, R.w,  0 - d0, lane);
        float Wn1 = warp_gather(R.x, R.y, R.z, R.w,  1 - d0, lane);
        float Wn2 = warp_gather(R.x, R.y, R.z, R.w,  2 - d0, lane);
        float Wn3 = warp_gather(R.x, R.y, R.z, R.w,  3 - d0, lane);

        #pragma unroll
        for (int s = 0; s < 6; s++) {
            const int d = d0 + s;
            float4 v;
            v.x = (w0     >= d) ? Wn0 : 0.0f;
            v.y = (w0 + 1 >= d) ? Wn1 : 0.0f;
            v.z = (w0 + 2 >= d) ? Wn2 : 0.0f;
            v.w = (w0 + 3 >= d) ? Wn3 : 0.0f;
            store_cs(op, v);
            op += HW;

            const float nw = warp_gather(R.x, R.y, R.z, R.w, -(d + 1), lane);
            Wn3 = Wn2; Wn2 = Wn1; Wn1 = Wn0; Wn0 = nw;
        }
    }
}

extern "C" void kernel_launch(void* const* d_in, const int* in_sizes, int n_in,
                              void* d_out, int out_size) {
    const float* left   = (const float*)d_in[0];
    const float* rleft  = (const float*)d_in[1];
    const float* right  = (const float*)d_in[2];
    const float* rright = (const float*)d_in[3];
    // d_in[4] = max_disp (int scalar) == 48, baked in as DD.

    const int grid = BB * CH_TOTAL * HH;   // 16384 CTAs
    cost_volume_kernel<<<grid, 256>>>(left, rleft, right, rright, (float*)d_out);
}